// round 2
// baseline (speedup 1.0000x reference)
#include <cuda_runtime.h>

#define N_USERS   50000
#define N_ITEMS   30000
#define N_ENT     150000
#define N_ASP     32
#define CH        64
#define N_EDGES   2000000
#define EPSF      1e-12f

#define SCAN_B    1024
#define NB1       147            // ceil(150000/1024)

// ---- static scratch (no runtime allocation allowed) ----
__device__ float g_ent_a[(size_t)N_ENT * CH];    // 38.4 MB ping
__device__ float g_ent_b[(size_t)N_ENT * CH];    // 38.4 MB pong
__device__ float g_eacc [(size_t)N_ITEMS * CH];  // sum of normalized entity hops (item slice)
__device__ int   g_deg [N_ENT];
__device__ int   g_row [N_ENT + 1];
__device__ int   g_cur [N_ENT];
__device__ int   g_bsum[256];
__device__ int   g_sorted[N_EDGES];              // packed: tail | (rel<<24)

// ---------------- CSR build ----------------
__global__ void k_zero_deg() {
    int i = blockIdx.x * blockDim.x + threadIdx.x;
    if (i < N_ENT) g_deg[i] = 0;
}

__global__ void k_hist(const int* __restrict__ head) {
    int stride = gridDim.x * blockDim.x;
    for (int e = blockIdx.x * blockDim.x + threadIdx.x; e < N_EDGES; e += stride)
        atomicAdd(&g_deg[head[e]], 1);
}

__global__ void k_scan1() {
    __shared__ int s[SCAN_B];
    int tid = threadIdx.x;
    int gid = blockIdx.x * SCAN_B + tid;
    int x = (gid < N_ENT) ? g_deg[gid] : 0;
    s[tid] = x;
    __syncthreads();
    for (int off = 1; off < SCAN_B; off <<= 1) {
        int y = (tid >= off) ? s[tid - off] : 0;
        __syncthreads();
        s[tid] += y;
        __syncthreads();
    }
    if (gid < N_ENT) g_row[gid] = s[tid] - x;    // exclusive
    if (tid == SCAN_B - 1) g_bsum[blockIdx.x] = s[tid];
}

__global__ void k_scan2() {
    __shared__ int s[256];
    int tid = threadIdx.x;
    int x = (tid < NB1) ? g_bsum[tid] : 0;
    s[tid] = x;
    __syncthreads();
    for (int off = 1; off < 256; off <<= 1) {
        int y = (tid >= off) ? s[tid - off] : 0;
        __syncthreads();
        s[tid] += y;
        __syncthreads();
    }
    if (tid < NB1) g_bsum[tid] = s[tid] - x;     // exclusive
}

__global__ void k_scan3() {
    int tid = threadIdx.x;
    int gid = blockIdx.x * SCAN_B + tid;
    if (gid < N_ENT) {
        int v = g_row[gid] + g_bsum[blockIdx.x];
        g_row[gid] = v;
        g_cur[gid] = v;
    }
    if (blockIdx.x == 0 && tid == 0) g_row[N_ENT] = N_EDGES;
}

__global__ void k_fill(const int* __restrict__ head, const int* __restrict__ tail,
                       const int* __restrict__ etype) {
    int stride = gridDim.x * blockDim.x;
    for (int e = blockIdx.x * blockDim.x + threadIdx.x; e < N_EDGES; e += stride) {
        int h = head[e];
        int p = atomicAdd(&g_cur[h], 1);
        g_sorted[p] = tail[e] | ((etype[e] - 2) << 24);
    }
}

// ---------------- entity hop: gather + mean + L2-normalize ----------------
// one warp per entity, float2 per lane (64 channels), 2 edges in flight
__global__ __launch_bounds__(256)
void k_hop(const float* __restrict__ ent0, const float* __restrict__ weight, int hop) {
    __shared__ float w[8 * CH];
    for (int i = threadIdx.x; i < 8 * CH; i += blockDim.x) w[i] = weight[i];
    __syncthreads();

    int warp = (blockIdx.x * blockDim.x + threadIdx.x) >> 5;
    int lane = threadIdx.x & 31;
    if (warp >= N_ENT) return;

    const float* in = (hop == 0) ? ent0 : (hop == 1 ? g_ent_a : g_ent_b);
    float*      out = (hop == 1) ? g_ent_b : g_ent_a;

    int beg = g_row[warp], end = g_row[warp + 1];
    float2 acc0 = make_float2(0.f, 0.f);
    float2 acc1 = make_float2(0.f, 0.f);

    for (int base = beg; base < end; base += 32) {
        int m = min(32, end - base);
        int pk_l = (lane < m) ? g_sorted[base + lane] : 0;
        int j = 0;
        for (; j + 1 < m; j += 2) {
            int pka = __shfl_sync(0xffffffffu, pk_l, j);
            int pkb = __shfl_sync(0xffffffffu, pk_l, j + 1);
            int ta = pka & 0xFFFFFF, ra = pka >> 24;
            int tb = pkb & 0xFFFFFF, rb = pkb >> 24;
            float2 va = ((const float2*)(in + (size_t)ta * CH))[lane];
            float2 vb = ((const float2*)(in + (size_t)tb * CH))[lane];
            float2 wa = ((const float2*)(w + ra * CH))[lane];
            float2 wb = ((const float2*)(w + rb * CH))[lane];
            acc0.x += va.x * wa.x; acc0.y += va.y * wa.y;
            acc1.x += vb.x * wb.x; acc1.y += vb.y * wb.y;
        }
        if (j < m) {
            int pk = __shfl_sync(0xffffffffu, pk_l, j);
            int t = pk & 0xFFFFFF, r = pk >> 24;
            float2 v  = ((const float2*)(in + (size_t)t * CH))[lane];
            float2 wr = ((const float2*)(w + r * CH))[lane];
            acc0.x += v.x * wr.x; acc0.y += v.y * wr.y;
        }
    }
    float2 acc = make_float2(acc0.x + acc1.x, acc0.y + acc1.y);

    int cnt = end - beg;
    float inv = 1.0f / (float)max(cnt, 1);
    acc.x *= inv; acc.y *= inv;

    float ss = acc.x * acc.x + acc.y * acc.y;
    #pragma unroll
    for (int o = 16; o; o >>= 1) ss += __shfl_xor_sync(0xffffffffu, ss, o);
    float s = 1.0f / fmaxf(sqrtf(ss), EPSF);

    float2 nv = make_float2(acc.x * s, acc.y * s);
    ((float2*)(out + (size_t)warp * CH))[lane] = nv;

    if (warp < N_ITEMS) {
        float2* ea = (float2*)(g_eacc + (size_t)warp * CH);
        if (hop == 0) {
            ea[lane] = nv;
        } else {
            float2 p = ea[lane];
            p.x += nv.x; p.y += nv.y;
            ea[lane] = p;
        }
    }
}

// ---------------- user output: user0 + 3*normalize(ua @ aspect) ----------------
__global__ __launch_bounds__(256)
void k_user(const float* __restrict__ user0, const float* __restrict__ ua,
            const float* __restrict__ asp, float* __restrict__ out) {
    __shared__ float sa[N_ASP * CH];
    for (int i = threadIdx.x; i < N_ASP * CH; i += blockDim.x) sa[i] = asp[i];
    __syncthreads();

    int warp = (blockIdx.x * blockDim.x + threadIdx.x) >> 5;
    int lane = threadIdx.x & 31;
    if (warp >= N_USERS) return;

    float a = ua[(size_t)warp * N_ASP + lane];
    float2 acc = make_float2(0.f, 0.f);
    #pragma unroll
    for (int k = 0; k < N_ASP; ++k) {
        float ak = __shfl_sync(0xffffffffu, a, k);
        float2 wv = ((const float2*)(sa + k * CH))[lane];
        acc.x += ak * wv.x;
        acc.y += ak * wv.y;
    }
    float ss = acc.x * acc.x + acc.y * acc.y;
    #pragma unroll
    for (int o = 16; o; o >>= 1) ss += __shfl_xor_sync(0xffffffffu, ss, o);
    float s = 3.0f / fmaxf(sqrtf(ss), EPSF);

    float2 u0 = ((const float2*)(user0 + (size_t)warp * CH))[lane];
    float2 r  = make_float2(u0.x + acc.x * s, u0.y + acc.y * s);
    ((float2*)(out + (size_t)warp * CH))[lane] = r;
}

// ---------------- item output: W1*(ent0+eacc) + W2*(item0 + 3*normalize(ia@asp)) ----
__global__ __launch_bounds__(256)
void k_item(const float* __restrict__ item0, const float* __restrict__ ent0,
            const float* __restrict__ ia, const float* __restrict__ asp,
            const float* __restrict__ W1p, const float* __restrict__ W2p,
            float* __restrict__ out) {
    __shared__ float sa[N_ASP * CH];
    for (int i = threadIdx.x; i < N_ASP * CH; i += blockDim.x) sa[i] = asp[i];
    __syncthreads();

    int warp = (blockIdx.x * blockDim.x + threadIdx.x) >> 5;
    int lane = threadIdx.x & 31;
    if (warp >= N_ITEMS) return;

    float a = ia[(size_t)warp * N_ASP + lane];
    float2 acc = make_float2(0.f, 0.f);
    #pragma unroll
    for (int k = 0; k < N_ASP; ++k) {
        float ak = __shfl_sync(0xffffffffu, a, k);
        float2 wv = ((const float2*)(sa + k * CH))[lane];
        acc.x += ak * wv.x;
        acc.y += ak * wv.y;
    }
    float ss = acc.x * acc.x + acc.y * acc.y;
    #pragma unroll
    for (int o = 16; o; o >>= 1) ss += __shfl_xor_sync(0xffffffffu, ss, o);
    float s = 3.0f / fmaxf(sqrtf(ss), EPSF);

    float w1 = W1p[0], w2 = W2p[0];
    float2 i0 = ((const float2*)(item0 + (size_t)warp * CH))[lane];
    float2 e0 = ((const float2*)(ent0  + (size_t)warp * CH))[lane];
    float2 ea = ((const float2*)(g_eacc + (size_t)warp * CH))[lane];

    float2 r;
    r.x = w1 * (e0.x + ea.x) + w2 * (i0.x + acc.x * s);
    r.y = w1 * (e0.y + ea.y) + w2 * (i0.y + acc.y * s);
    ((float2*)(out + (size_t)warp * CH))[lane] = r;
}

// ---------------- launch ----------------
extern "C" void kernel_launch(void* const* d_in, const int* in_sizes, int n_in,
                              void* d_out, int out_size) {
    const float* user0 = (const float*)d_in[0];
    const float* item0 = (const float*)d_in[1];
    const float* ent0  = (const float*)d_in[2];
    const float* asp   = (const float*)d_in[3];
    const float* ua    = (const float*)d_in[4];
    const float* ia    = (const float*)d_in[5];
    const float* wt    = (const float*)d_in[6];
    const float* W1p   = (const float*)d_in[7];
    const float* W2p   = (const float*)d_in[8];
    const int*   eidx  = (const int*)d_in[9];
    const int*   etyp  = (const int*)d_in[10];
    const int*   head  = eidx;
    const int*   tail  = eidx + N_EDGES;
    float*       out   = (float*)d_out;

    // CSR build
    k_zero_deg<<<(N_ENT + 255) / 256, 256>>>();
    k_hist<<<1024, 256>>>(head);
    k_scan1<<<NB1, SCAN_B>>>();
    k_scan2<<<1, 256>>>();
    k_scan3<<<NB1, SCAN_B>>>();
    k_fill<<<1024, 256>>>(head, tail, etyp);

    // 3 entity hops (warp per entity)
    const int hop_blocks = (N_ENT * 32 + 255) / 256;
    k_hop<<<hop_blocks, 256>>>(ent0, wt, 0);
    k_hop<<<hop_blocks, 256>>>(ent0, wt, 1);
    k_hop<<<hop_blocks, 256>>>(ent0, wt, 2);

    // outputs: item_res first, then user_res
    k_item<<<(N_ITEMS * 32 + 255) / 256, 256>>>(item0, ent0, ia, asp, W1p, W2p, out);
    k_user<<<(N_USERS * 32 + 255) / 256, 256>>>(user0, ua, asp, out + (size_t)N_ITEMS * CH);
}